// round 3
// baseline (speedup 1.0000x reference)
#include <cuda_runtime.h>
#include <cstdint>

// ---------------------------------------------------------------------------
// Encoder_35064113004946: 2x (EdgeConv -> Conv1d(k=5,pad=2)+ReLU+MaxPool1d(2))
//
// EdgeConv trick: cat[x_i, x_j - x_i] @ W = x_i @ W_top + (x_j - x_i) @ W_bot
//   => per-node A = X@W_top, B = X@W_bot; per-edge msg = relu(A[d]+B[s]-B[d]+b)
//   => segment_max == atomicMax(float-as-int) into 0-initialized out (msgs>=0)
// Conv1d+pool: GEMM over K = 5*256 with shifted-row A gather, relu+maxpool
//   fused in epilogue via shfl (pool partner row gid^1 lives in lane^4).
// GEMMs run on the tensor pipe: tf32 mma.sync.m16n8k8 (HMMA), fp32 accum.
// ---------------------------------------------------------------------------

#define T_      128
#define F_      128
#define H_      256
#define M0      32768          // B*N*T nodes, layer 0
#define E0      262144
#define M1      16384          // after pool /2
#define E1      131072

// scratch layout (floats)
#define OFF_X0     0
#define SZ_X0      (M0 * F_)
#define OFF_AB0    (OFF_X0 + SZ_X0)
#define SZ_AB0     (M0 * 512)
#define OFF_OUT0   (OFF_AB0 + SZ_AB0)
#define SZ_OUT0    (M0 * 256)
#define OFF_X1     (OFF_OUT0 + SZ_OUT0)
#define SZ_X1      (M1 * 256)
#define OFF_AB1    (OFF_X1 + SZ_X1)
#define SZ_AB1     (M1 * 512)
#define OFF_OUT1   (OFF_AB1 + SZ_AB1)
#define SZ_OUT1    (M1 * 256)
#define OFF_WCAT0  (OFF_OUT1 + SZ_OUT1)
#define SZ_WCAT0   (128 * 512)
#define OFF_WCAT1  (OFF_WCAT0 + SZ_WCAT0)
#define SZ_WCAT1   (256 * 512)
#define OFF_WT0    (OFF_WCAT1 + SZ_WCAT1)
#define SZ_WT      (1280 * 256)
#define OFF_WT1    (OFF_WT0 + SZ_WT)
#define SCRATCH_TOTAL (OFF_WT1 + SZ_WT)

__device__ float g_scratch[SCRATCH_TOTAL];

// ---------------------------------------------------------------------------
__device__ __forceinline__ unsigned f2tf32(float x) {
    unsigned r;
    asm("cvt.rna.tf32.f32 %0, %1;" : "=r"(r) : "f"(x));
    return r;
}

__device__ __forceinline__ void mma_tf32(float* d, const unsigned* a, const unsigned* b) {
    asm volatile(
        "mma.sync.aligned.m16n8k8.row.col.f32.tf32.tf32.f32 "
        "{%0,%1,%2,%3}, {%4,%5,%6,%7}, {%8,%9}, {%0,%1,%2,%3};\n"
        : "+f"(d[0]), "+f"(d[1]), "+f"(d[2]), "+f"(d[3])
        : "r"(a[0]), "r"(a[1]), "r"(a[2]), "r"(a[3]), "r"(b[0]), "r"(b[1]));
}

// ---------------------------------------------------------------------------
// input permute: data[T,B,N,F] -> x0[(b*32+n)*128 + t, f]
__global__ void permute_in(const float* __restrict__ data, float* __restrict__ x0) {
    int idx = blockIdx.x * 256 + threadIdx.x;
    int f    = idx & 127;
    int node = idx >> 7;
    int t    = node & 127;
    int bn   = node >> 7;
    int b    = bn >> 5;
    int n    = bn & 31;
    x0[idx] = data[(((t * 8 + b) * 32 + n) << 7) + f];
}

// ---------------------------------------------------------------------------
// weight prep: Wcat = [W_top | W_bot] (K x 512); Wt[(k*256+i)*256+o] = Wc[o,i,k]
__global__ void prep_weights(const float* __restrict__ W0, const float* __restrict__ W1,
                             const float* __restrict__ Wc0, const float* __restrict__ Wc1,
                             float* __restrict__ Wcat0, float* __restrict__ Wcat1,
                             float* __restrict__ Wt0, float* __restrict__ Wt1) {
    int idx = blockIdx.x * 256 + threadIdx.x;
    if (idx < 65536) {
        int f = idx >> 9, h = idx & 511;
        Wcat0[idx] = (h < 256) ? W0[f * 256 + h] : W0[(128 + f) * 256 + (h - 256)];
        return;
    }
    idx -= 65536;
    if (idx < 131072) {
        int i = idx >> 9, h = idx & 511;
        Wcat1[idx] = (h < 256) ? W1[i * 256 + h] : W1[(256 + i) * 256 + (h - 256)];
        return;
    }
    idx -= 131072;
    if (idx < 327680) {
        int kk = idx >> 8, o = idx & 255;
        int k = kk >> 8, i = kk & 255;
        Wt0[idx] = Wc0[(o * 256 + i) * 5 + k];
        return;
    }
    idx -= 327680;
    if (idx < 327680) {
        int kk = idx >> 8, o = idx & 255;
        int k = kk >> 8, i = kk & 255;
        Wt1[idx] = Wc1[(o * 256 + i) * 5 + k];
    }
}

// ---------------------------------------------------------------------------
__global__ void zero_kernel(float4* __restrict__ p) {
    p[blockIdx.x * 256 + threadIdx.x] = make_float4(0.f, 0.f, 0.f, 0.f);
}

// ---------------------------------------------------------------------------
// tf32 tensor-core SGEMM: C[M,N] = A[M,K] @ B[K,N]; M%128==0, N%128==0, K%16==0
// Block tile 128x128, 8 warps, warp tile 32x64 (2x8 of m16n8k8).
__global__ __launch_bounds__(256)
void sgemm_tf32(const float* __restrict__ A, const float* __restrict__ B,
                float* __restrict__ C, int N, int K) {
    __shared__ unsigned As[16][136];   // [k][m], stride 136 -> conflict-free frags
    __shared__ unsigned Bs[16][136];   // [k][n]
    int tid = threadIdx.x;
    int lane = tid & 31, wid = tid >> 5;
    int wm = wid & 3, wn = wid >> 2;
    int gid = lane >> 2, tg = lane & 3;
    int bm = blockIdx.y * 128, bn = blockIdx.x * 128;
    int arow = tid >> 2, acol = (tid & 3) << 2;
    int brow = tid >> 5, bcol = (tid & 31) << 2;
    float acc[2][8][4] = {};

    for (int k0 = 0; k0 < K; k0 += 16) {
#pragma unroll
        for (int rr = 0; rr < 2; rr++) {
            int row = arow + rr * 64;
            float4 v = *(const float4*)(A + (size_t)(bm + row) * K + k0 + acol);
            As[acol + 0][row] = f2tf32(v.x);
            As[acol + 1][row] = f2tf32(v.y);
            As[acol + 2][row] = f2tf32(v.z);
            As[acol + 3][row] = f2tf32(v.w);
        }
#pragma unroll
        for (int rr = 0; rr < 2; rr++) {
            int row = brow + rr * 8;
            float4 v = *(const float4*)(B + (size_t)(k0 + row) * N + bn + bcol);
            uint4 u = make_uint4(f2tf32(v.x), f2tf32(v.y), f2tf32(v.z), f2tf32(v.w));
            *(uint4*)&Bs[row][bcol] = u;
        }
        __syncthreads();
#pragma unroll
        for (int kk = 0; kk < 16; kk += 8) {
            unsigned a[2][4], b[8][2];
#pragma unroll
            for (int mi = 0; mi < 2; mi++) {
                int m0 = wm * 32 + mi * 16 + gid;
                a[mi][0] = As[kk + tg][m0];
                a[mi][1] = As[kk + tg][m0 + 8];
                a[mi][2] = As[kk + tg + 4][m0];
                a[mi][3] = As[kk + tg + 4][m0 + 8];
            }
#pragma unroll
            for (int ni = 0; ni < 8; ni++) {
                int n0 = wn * 64 + ni * 8 + gid;
                b[ni][0] = Bs[kk + tg][n0];
                b[ni][1] = Bs[kk + tg + 4][n0];
            }
#pragma unroll
            for (int mi = 0; mi < 2; mi++)
#pragma unroll
                for (int ni = 0; ni < 8; ni++)
                    mma_tf32(acc[mi][ni], a[mi], b[ni]);
        }
        __syncthreads();
    }
#pragma unroll
    for (int mi = 0; mi < 2; mi++) {
        int r0 = bm + wm * 32 + mi * 16 + gid;
#pragma unroll
        for (int ni = 0; ni < 8; ni++) {
            int c0 = bn + wn * 64 + ni * 8 + tg * 2;
            *(float2*)(C + (size_t)r0 * N + c0) = make_float2(acc[mi][ni][0], acc[mi][ni][1]);
            *(float2*)(C + (size_t)(r0 + 8) * N + c0) = make_float2(acc[mi][ni][2], acc[mi][ni][3]);
        }
    }
}

// ---------------------------------------------------------------------------
// edge aggregation: out[dst] = max(out[dst], relu(A[dst]+B[src]-B[dst]+bias))
__global__ void edge_agg(const int* __restrict__ ei, int E,
                         const float* __restrict__ AB,
                         const float* __restrict__ bias,
                         float* __restrict__ out) {
    int warp = (blockIdx.x * blockDim.x + threadIdx.x) >> 5;
    if (warp >= E) return;
    int lane = threadIdx.x & 31;
    int src = __ldg(ei + warp);
    int dst = __ldg(ei + E + warp);
    const float* basd = AB + (size_t)dst * 512;
    const float* bass = AB + (size_t)src * 512;
    int* po = (int*)(out + (size_t)dst * 256);
#pragma unroll
    for (int h = 0; h < 2; h++) {
        int c = lane * 4 + h * 128;
        float4 a  = *(const float4*)(basd + c);
        float4 bd = *(const float4*)(basd + 256 + c);
        float4 bs = *(const float4*)(bass + 256 + c);
        float4 bb = *(const float4*)(bias + c);
        float v0 = a.x + bs.x - bd.x + bb.x;
        float v1 = a.y + bs.y - bd.y + bb.y;
        float v2 = a.z + bs.z - bd.z + bb.z;
        float v3 = a.w + bs.w - bd.w + bb.w;
        if (v0 > 0.f) atomicMax(po + c + 0, __float_as_int(v0));
        if (v1 > 0.f) atomicMax(po + c + 1, __float_as_int(v1));
        if (v2 > 0.f) atomicMax(po + c + 2, __float_as_int(v2));
        if (v3 > 0.f) atomicMax(po + c + 3, __float_as_int(v3));
    }
}

// ---------------------------------------------------------------------------
// conv1d(k=5,pad=2)+relu+maxpool(2) as tf32 tensor-core GEMM.
// X: [M, 256] (rows = bn_node*L + l), Wt: [1280, 256], Y: [M/2, 256]
template <int L>
__global__ __launch_bounds__(256)
void convpool_tf32(const float* __restrict__ X, const float* __restrict__ Wt,
                   const float* __restrict__ bias, float* __restrict__ Y) {
    __shared__ unsigned As[16][136];
    __shared__ unsigned Bs[16][136];
    int tid = threadIdx.x;
    int lane = tid & 31, wid = tid >> 5;
    int wm = wid & 3, wn = wid >> 2;
    int gid = lane >> 2, tg = lane & 3;
    int bm = blockIdx.y * 128, bn = blockIdx.x * 128;
    int arow = tid >> 2, acol = (tid & 3) << 2;
    int brow = tid >> 5, bcol = (tid & 31) << 2;
    float acc[2][8][4] = {};

    for (int k0 = 0; k0 < 1280; k0 += 16) {
        int kshift = (k0 >> 8) - 2;
        int i0 = k0 & 255;
#pragma unroll
        for (int rr = 0; rr < 2; rr++) {
            int rm = bm + arow + rr * 64;
            int srow = rm + kshift;
            float4 v = make_float4(0.f, 0.f, 0.f, 0.f);
            if (srow >= 0 && (srow / L) == (rm / L))
                v = *(const float4*)(X + (size_t)srow * 256 + i0 + acol);
            int row = arow + rr * 64;
            As[acol + 0][row] = f2tf32(v.x);
            As[acol + 1][row] = f2tf32(v.y);
            As[acol + 2][row] = f2tf32(v.z);
            As[acol + 3][row] = f2tf32(v.w);
        }
#pragma unroll
        for (int rr = 0; rr < 2; rr++) {
            int row = brow + rr * 8;
            float4 v = *(const float4*)(Wt + (size_t)(k0 + row) * 256 + bn + bcol);
            uint4 u = make_uint4(f2tf32(v.x), f2tf32(v.y), f2tf32(v.z), f2tf32(v.w));
            *(uint4*)&Bs[row][bcol] = u;
        }
        __syncthreads();
#pragma unroll
        for (int kk = 0; kk < 16; kk += 8) {
            unsigned a[2][4], b[8][2];
#pragma unroll
            for (int mi = 0; mi < 2; mi++) {
                int m0 = wm * 32 + mi * 16 + gid;
                a[mi][0] = As[kk + tg][m0];
                a[mi][1] = As[kk + tg][m0 + 8];
                a[mi][2] = As[kk + tg + 4][m0];
                a[mi][3] = As[kk + tg + 4][m0 + 8];
            }
#pragma unroll
            for (int ni = 0; ni < 8; ni++) {
                int n0 = wn * 64 + ni * 8 + gid;
                b[ni][0] = Bs[kk + tg][n0];
                b[ni][1] = Bs[kk + tg + 4][n0];
            }
#pragma unroll
            for (int mi = 0; mi < 2; mi++)
#pragma unroll
                for (int ni = 0; ni < 8; ni++)
                    mma_tf32(acc[mi][ni], a[mi], b[ni]);
        }
        __syncthreads();
    }

    // epilogue: +bias, relu, pool rows (2r,2r+1); partner row is in lane^4
    bool write = (gid & 1) == 0;
#pragma unroll
    for (int mi = 0; mi < 2; mi++) {
        int rbase = bm + wm * 32 + mi * 16 + gid;
#pragma unroll
        for (int ni = 0; ni < 8; ni++) {
            int c0 = bn + wn * 64 + ni * 8 + tg * 2;
            float b0 = bias[c0], b1 = bias[c0 + 1];
            float u0 = fmaxf(acc[mi][ni][0] + b0, 0.f);
            float u1 = fmaxf(acc[mi][ni][1] + b1, 0.f);
            float u2 = fmaxf(acc[mi][ni][2] + b0, 0.f);
            float u3 = fmaxf(acc[mi][ni][3] + b1, 0.f);
            float p0 = fmaxf(u0, __shfl_xor_sync(0xffffffffu, u0, 4));
            float p1 = fmaxf(u1, __shfl_xor_sync(0xffffffffu, u1, 4));
            float p2 = fmaxf(u2, __shfl_xor_sync(0xffffffffu, u2, 4));
            float p3 = fmaxf(u3, __shfl_xor_sync(0xffffffffu, u3, 4));
            if (write) {
                *(float2*)(Y + (size_t)(rbase >> 1) * 256 + c0) = make_float2(p0, p1);
                *(float2*)(Y + (size_t)((rbase + 8) >> 1) * 256 + c0) = make_float2(p2, p3);
            }
        }
    }
}

// ---------------------------------------------------------------------------
extern "C" void kernel_launch(void* const* d_in, const int* in_sizes, int n_in,
                              void* d_out, int out_size) {
    const float* data = (const float*)d_in[0];
    const int*   ei0  = (const int*)d_in[2];
    const int*   ei1  = (const int*)d_in[3];
    const float* W0   = (const float*)d_in[4];
    const float* b0   = (const float*)d_in[5];
    const float* Wc0  = (const float*)d_in[6];
    const float* bc0  = (const float*)d_in[7];
    const float* W1   = (const float*)d_in[8];
    const float* b1   = (const float*)d_in[9];
    const float* Wc1  = (const float*)d_in[10];
    const float* bc1  = (const float*)d_in[11];
    float* out = (float*)d_out;

    void* sp = nullptr;
    cudaGetSymbolAddress(&sp, g_scratch);
    float* S     = (float*)sp;
    float* x0    = S + OFF_X0;
    float* AB0   = S + OFF_AB0;
    float* out0  = S + OFF_OUT0;
    float* x1    = S + OFF_X1;
    float* AB1   = S + OFF_AB1;
    float* out1  = S + OFF_OUT1;
    float* Wcat0 = S + OFF_WCAT0;
    float* Wcat1 = S + OFF_WCAT1;
    float* Wt0   = S + OFF_WT0;
    float* Wt1   = S + OFF_WT1;

    prep_weights<<<3328, 256>>>(W0, W1, Wc0, Wc1, Wcat0, Wcat1, Wt0, Wt1);
    permute_in<<<(M0 * F_) / 256, 256>>>(data, x0);
    zero_kernel<<<SZ_OUT0 / 1024, 256>>>((float4*)out0);
    zero_kernel<<<SZ_OUT1 / 1024, 256>>>((float4*)out1);

    // layer 0
    sgemm_tf32<<<dim3(4, M0 / 128), 256>>>(x0, Wcat0, AB0, 512, 128);
    edge_agg<<<E0 / 8, 256>>>(ei0, E0, AB0, b0, out0);
    convpool_tf32<128><<<dim3(2, M0 / 128), 256>>>(out0, Wt0, bc0, x1);

    // layer 1
    sgemm_tf32<<<dim3(4, M1 / 128), 256>>>(x1, Wcat1, AB1, 512, 256);
    edge_agg<<<E1 / 8, 256>>>(ei1, E1, AB1, b1, out1);
    convpool_tf32<64><<<dim3(2, M1 / 128), 256>>>(out1, Wt1, bc1, out);
}

// round 4
// speedup vs baseline: 1.0033x; 1.0033x over previous
#include <cuda_runtime.h>
#include <cstdint>

// ---------------------------------------------------------------------------
// Encoder_35064113004946: 2x (EdgeConv -> Conv1d(k=5,pad=2)+ReLU+MaxPool1d(2))
//
// EdgeConv trick: cat[x_i, x_j - x_i] @ W = x_i @ W_top + (x_j - x_i) @ W_bot
//   => per-node A = X@W_top, B = X@W_bot; per-edge msg = relu(A[d]+B[s]-B[d]+b)
//   => segment_max == atomicMax(float-as-int) into 0-initialized out (msgs>=0)
// Conv1d+pool: GEMM over K = 5*256 with shifted-row A gather, relu+maxpool
//   fused in epilogue via shfl (pool partner row gid^1 lives in lane^4).
// GEMMs run on the tensor pipe: tf32 mma.sync.m16n8k8 (HMMA), fp32 accum.
// ---------------------------------------------------------------------------

#define T_      128
#define F_      128
#define H_      256
#define M0      32768          // B*N*T nodes, layer 0
#define E0      262144
#define M1      16384          // after pool /2
#define E1      131072

// scratch layout (floats)
#define OFF_X0     0
#define SZ_X0      (M0 * F_)
#define OFF_AB0    (OFF_X0 + SZ_X0)
#define SZ_AB0     (M0 * 512)
#define OFF_OUT0   (OFF_AB0 + SZ_AB0)
#define SZ_OUT0    (M0 * 256)
#define OFF_X1     (OFF_OUT0 + SZ_OUT0)
#define SZ_X1      (M1 * 256)
#define OFF_AB1    (OFF_X1 + SZ_X1)
#define SZ_AB1     (M1 * 512)
#define OFF_OUT1   (OFF_AB1 + SZ_AB1)
#define SZ_OUT1    (M1 * 256)
#define OFF_WCAT0  (OFF_OUT1 + SZ_OUT1)
#define SZ_WCAT0   (128 * 512)
#define OFF_WCAT1  (OFF_WCAT0 + SZ_WCAT0)
#define SZ_WCAT1   (256 * 512)
#define OFF_WT0    (OFF_WCAT1 + SZ_WCAT1)
#define SZ_WT      (1280 * 256)
#define OFF_WT1    (OFF_WT0 + SZ_WT)
#define SCRATCH_TOTAL (OFF_WT1 + SZ_WT)

__device__ float g_scratch[SCRATCH_TOTAL];

// ---------------------------------------------------------------------------
__device__ __forceinline__ unsigned f2tf32(float x) {
    unsigned r;
    asm("cvt.rna.tf32.f32 %0, %1;" : "=r"(r) : "f"(x));
    return r;
}

__device__ __forceinline__ void mma_tf32(float* d, const unsigned* a, const unsigned* b) {
    asm volatile(
        "mma.sync.aligned.m16n8k8.row.col.f32.tf32.tf32.f32 "
        "{%0,%1,%2,%3}, {%4,%5,%6,%7}, {%8,%9}, {%0,%1,%2,%3};\n"
        : "+f"(d[0]), "+f"(d[1]), "+f"(d[2]), "+f"(d[3])
        : "r"(a[0]), "r"(a[1]), "r"(a[2]), "r"(a[3]), "r"(b[0]), "r"(b[1]));
}

// ---------------------------------------------------------------------------
// input permute: data[T,B,N,F] -> x0[(b*32+n)*128 + t, f]
__global__ void permute_in(const float* __restrict__ data, float* __restrict__ x0) {
    int idx = blockIdx.x * 256 + threadIdx.x;
    int f    = idx & 127;
    int node = idx >> 7;
    int t    = node & 127;
    int bn   = node >> 7;
    int b    = bn >> 5;
    int n    = bn & 31;
    x0[idx] = data[(((t * 8 + b) * 32 + n) << 7) + f];
}

// ---------------------------------------------------------------------------
// weight prep: Wcat = [W_top | W_bot] (K x 512); Wt[(k*256+i)*256+o] = Wc[o,i,k]
__global__ void prep_weights(const float* __restrict__ W0, const float* __restrict__ W1,
                             const float* __restrict__ Wc0, const float* __restrict__ Wc1,
                             float* __restrict__ Wcat0, float* __restrict__ Wcat1,
                             float* __restrict__ Wt0, float* __restrict__ Wt1) {
    int idx = blockIdx.x * 256 + threadIdx.x;
    if (idx < 65536) {
        int f = idx >> 9, h = idx & 511;
        Wcat0[idx] = (h < 256) ? W0[f * 256 + h] : W0[(128 + f) * 256 + (h - 256)];
        return;
    }
    idx -= 65536;
    if (idx < 131072) {
        int i = idx >> 9, h = idx & 511;
        Wcat1[idx] = (h < 256) ? W1[i * 256 + h] : W1[(256 + i) * 256 + (h - 256)];
        return;
    }
    idx -= 131072;
    if (idx < 327680) {
        int kk = idx >> 8, o = idx & 255;
        int k = kk >> 8, i = kk & 255;
        Wt0[idx] = Wc0[(o * 256 + i) * 5 + k];
        return;
    }
    idx -= 327680;
    if (idx < 327680) {
        int kk = idx >> 8, o = idx & 255;
        int k = kk >> 8, i = kk & 255;
        Wt1[idx] = Wc1[(o * 256 + i) * 5 + k];
    }
}

// ---------------------------------------------------------------------------
__global__ void zero_kernel(float4* __restrict__ p) {
    p[blockIdx.x * 256 + threadIdx.x] = make_float4(0.f, 0.f, 0.f, 0.f);
}

// ---------------------------------------------------------------------------
// tf32 tensor-core SGEMM: C[M,N] = A[M,K] @ B[K,N]; M%128==0, N%128==0, K%16==0
// Block tile 128x128, 8 warps, warp tile 32x64 (2x8 of m16n8k8).
__global__ __launch_bounds__(256)
void sgemm_tf32(const float* __restrict__ A, const float* __restrict__ B,
                float* __restrict__ C, int N, int K) {
    __shared__ unsigned As[16][136];   // [k][m], stride 136 -> conflict-free frags
    __shared__ unsigned Bs[16][136];   // [k][n]
    int tid = threadIdx.x;
    int lane = tid & 31, wid = tid >> 5;
    int wm = wid & 3, wn = wid >> 2;
    int gid = lane >> 2, tg = lane & 3;
    int bm = blockIdx.y * 128, bn = blockIdx.x * 128;
    int arow = tid >> 2, acol = (tid & 3) << 2;
    int brow = tid >> 5, bcol = (tid & 31) << 2;
    float acc[2][8][4] = {};

    for (int k0 = 0; k0 < K; k0 += 16) {
#pragma unroll
        for (int rr = 0; rr < 2; rr++) {
            int row = arow + rr * 64;
            float4 v = *(const float4*)(A + (size_t)(bm + row) * K + k0 + acol);
            As[acol + 0][row] = f2tf32(v.x);
            As[acol + 1][row] = f2tf32(v.y);
            As[acol + 2][row] = f2tf32(v.z);
            As[acol + 3][row] = f2tf32(v.w);
        }
#pragma unroll
        for (int rr = 0; rr < 2; rr++) {
            int row = brow + rr * 8;
            float4 v = *(const float4*)(B + (size_t)(k0 + row) * N + bn + bcol);
            uint4 u = make_uint4(f2tf32(v.x), f2tf32(v.y), f2tf32(v.z), f2tf32(v.w));
            *(uint4*)&Bs[row][bcol] = u;
        }
        __syncthreads();
#pragma unroll
        for (int kk = 0; kk < 16; kk += 8) {
            unsigned a[2][4], b[8][2];
#pragma unroll
            for (int mi = 0; mi < 2; mi++) {
                int m0 = wm * 32 + mi * 16 + gid;
                a[mi][0] = As[kk + tg][m0];
                a[mi][1] = As[kk + tg][m0 + 8];
                a[mi][2] = As[kk + tg + 4][m0];
                a[mi][3] = As[kk + tg + 4][m0 + 8];
            }
#pragma unroll
            for (int ni = 0; ni < 8; ni++) {
                int n0 = wn * 64 + ni * 8 + gid;
                b[ni][0] = Bs[kk + tg][n0];
                b[ni][1] = Bs[kk + tg + 4][n0];
            }
#pragma unroll
            for (int mi = 0; mi < 2; mi++)
#pragma unroll
                for (int ni = 0; ni < 8; ni++)
                    mma_tf32(acc[mi][ni], a[mi], b[ni]);
        }
        __syncthreads();
    }
#pragma unroll
    for (int mi = 0; mi < 2; mi++) {
        int r0 = bm + wm * 32 + mi * 16 + gid;
#pragma unroll
        for (int ni = 0; ni < 8; ni++) {
            int c0 = bn + wn * 64 + ni * 8 + tg * 2;
            *(float2*)(C + (size_t)r0 * N + c0) = make_float2(acc[mi][ni][0], acc[mi][ni][1]);
            *(float2*)(C + (size_t)(r0 + 8) * N + c0) = make_float2(acc[mi][ni][2], acc[mi][ni][3]);
        }
    }
}

// ---------------------------------------------------------------------------
// edge aggregation: out[dst] = max(out[dst], relu(A[dst]+B[src]-B[dst]+bias))
__global__ void edge_agg(const int* __restrict__ ei, int E,
                         const float* __restrict__ AB,
                         const float* __restrict__ bias,
                         float* __restrict__ out) {
    int warp = (blockIdx.x * blockDim.x + threadIdx.x) >> 5;
    if (warp >= E) return;
    int lane = threadIdx.x & 31;
    int src = __ldg(ei + warp);
    int dst = __ldg(ei + E + warp);
    const float* basd = AB + (size_t)dst * 512;
    const float* bass = AB + (size_t)src * 512;
    int* po = (int*)(out + (size_t)dst * 256);
#pragma unroll
    for (int h = 0; h < 2; h++) {
        int c = lane * 4 + h * 128;
        float4 a  = *(const float4*)(basd + c);
        float4 bd = *(const float4*)(basd + 256 + c);
        float4 bs = *(const float4*)(bass + 256 + c);
        float4 bb = *(const float4*)(bias + c);
        float v0 = a.x + bs.x - bd.x + bb.x;
        float v1 = a.y + bs.y - bd.y + bb.y;
        float v2 = a.z + bs.z - bd.z + bb.z;
        float v3 = a.w + bs.w - bd.w + bb.w;
        if (v0 > 0.f) atomicMax(po + c + 0, __float_as_int(v0));
        if (v1 > 0.f) atomicMax(po + c + 1, __float_as_int(v1));
        if (v2 > 0.f) atomicMax(po + c + 2, __float_as_int(v2));
        if (v3 > 0.f) atomicMax(po + c + 3, __float_as_int(v3));
    }
}

// ---------------------------------------------------------------------------
// conv1d(k=5,pad=2)+relu+maxpool(2) as tf32 tensor-core GEMM.
// X: [M, 256] (rows = bn_node*L + l), Wt: [1280, 256], Y: [M/2, 256]
template <int L>
__global__ __launch_bounds__(256)
void convpool_tf32(const float* __restrict__ X, const float* __restrict__ Wt,
                   const float* __restrict__ bias, float* __restrict__ Y) {
    __shared__ unsigned As[16][136];
    __shared__ unsigned Bs[16][136];
    int tid = threadIdx.x;
    int lane = tid & 31, wid = tid >> 5;
    int wm = wid & 3, wn = wid >> 2;
    int gid = lane >> 2, tg = lane & 3;
    int bm = blockIdx.y * 128, bn = blockIdx.x * 128;
    int arow = tid >> 2, acol = (tid & 3) << 2;
    int brow = tid >> 5, bcol = (tid & 31) << 2;
    float acc[2][8][4] = {};

    for (int k0 = 0; k0 < 1280; k0 += 16) {
        int kshift = (k0 >> 8) - 2;
        int i0 = k0 & 255;
#pragma unroll
        for (int rr = 0; rr < 2; rr++) {
            int rm = bm + arow + rr * 64;
            int srow = rm + kshift;
            float4 v = make_float4(0.f, 0.f, 0.f, 0.f);
            if (srow >= 0 && (srow / L) == (rm / L))
                v = *(const float4*)(X + (size_t)srow * 256 + i0 + acol);
            int row = arow + rr * 64;
            As[acol + 0][row] = f2tf32(v.x);
            As[acol + 1][row] = f2tf32(v.y);
            As[acol + 2][row] = f2tf32(v.z);
            As[acol + 3][row] = f2tf32(v.w);
        }
#pragma unroll
        for (int rr = 0; rr < 2; rr++) {
            int row = brow + rr * 8;
            float4 v = *(const float4*)(Wt + (size_t)(k0 + row) * 256 + bn + bcol);
            uint4 u = make_uint4(f2tf32(v.x), f2tf32(v.y), f2tf32(v.z), f2tf32(v.w));
            *(uint4*)&Bs[row][bcol] = u;
        }
        __syncthreads();
#pragma unroll
        for (int kk = 0; kk < 16; kk += 8) {
            unsigned a[2][4], b[8][2];
#pragma unroll
            for (int mi = 0; mi < 2; mi++) {
                int m0 = wm * 32 + mi * 16 + gid;
                a[mi][0] = As[kk + tg][m0];
                a[mi][1] = As[kk + tg][m0 + 8];
                a[mi][2] = As[kk + tg + 4][m0];
                a[mi][3] = As[kk + tg + 4][m0 + 8];
            }
#pragma unroll
            for (int ni = 0; ni < 8; ni++) {
                int n0 = wn * 64 + ni * 8 + gid;
                b[ni][0] = Bs[kk + tg][n0];
                b[ni][1] = Bs[kk + tg + 4][n0];
            }
#pragma unroll
            for (int mi = 0; mi < 2; mi++)
#pragma unroll
                for (int ni = 0; ni < 8; ni++)
                    mma_tf32(acc[mi][ni], a[mi], b[ni]);
        }
        __syncthreads();
    }

    // epilogue: +bias, relu, pool rows (2r,2r+1); partner row is in lane^4
    bool write = (gid & 1) == 0;
#pragma unroll
    for (int mi = 0; mi < 2; mi++) {
        int rbase = bm + wm * 32 + mi * 16 + gid;
#pragma unroll
        for (int ni = 0; ni < 8; ni++) {
            int c0 = bn + wn * 64 + ni * 8 + tg * 2;
            float b0 = bias[c0], b1 = bias[c0 + 1];
            float u0 = fmaxf(acc[mi][ni][0] + b0, 0.f);
            float u1 = fmaxf(acc[mi][ni][1] + b1, 0.f);
            float u2 = fmaxf(acc[mi][ni][2] + b0, 0.f);
            float u3 = fmaxf(acc[mi][ni][3] + b1, 0.f);
            float p0 = fmaxf(u0, __shfl_xor_sync(0xffffffffu, u0, 4));
            float p1 = fmaxf(u1, __shfl_xor_sync(0xffffffffu, u1, 4));
            float p2 = fmaxf(u2, __shfl_xor_sync(0xffffffffu, u2, 4));
            float p3 = fmaxf(u3, __shfl_xor_sync(0xffffffffu, u3, 4));
            if (write) {
                *(float2*)(Y + (size_t)(rbase >> 1) * 256 + c0) = make_float2(p0, p1);
                *(float2*)(Y + (size_t)((rbase + 8) >> 1) * 256 + c0) = make_float2(p2, p3);
            }
        }
    }
}

// ---------------------------------------------------------------------------
extern "C" void kernel_launch(void* const* d_in, const int* in_sizes, int n_in,
                              void* d_out, int out_size) {
    const float* data = (const float*)d_in[0];
    const int*   ei0  = (const int*)d_in[2];
    const int*   ei1  = (const int*)d_in[3];
    const float* W0   = (const float*)d_in[4];
    const float* b0   = (const float*)d_in[5];
    const float* Wc0  = (const float*)d_in[6];
    const float* bc0  = (const float*)d_in[7];
    const float* W1   = (const float*)d_in[8];
    const float* b1   = (const float*)d_in[9];
    const float* Wc1  = (const float*)d_in[10];
    const float* bc1  = (const float*)d_in[11];
    float* out = (float*)d_out;

    void* sp = nullptr;
    cudaGetSymbolAddress(&sp, g_scratch);
    float* S     = (float*)sp;
    float* x0    = S + OFF_X0;
    float* AB0   = S + OFF_AB0;
    float* out0  = S + OFF_OUT0;
    float* x1    = S + OFF_X1;
    float* AB1   = S + OFF_AB1;
    float* out1  = S + OFF_OUT1;
    float* Wcat0 = S + OFF_WCAT0;
    float* Wcat1 = S + OFF_WCAT1;
    float* Wt0   = S + OFF_WT0;
    float* Wt1   = S + OFF_WT1;

    prep_weights<<<3328, 256>>>(W0, W1, Wc0, Wc1, Wcat0, Wcat1, Wt0, Wt1);
    permute_in<<<(M0 * F_) / 256, 256>>>(data, x0);
    zero_kernel<<<SZ_OUT0 / 1024, 256>>>((float4*)out0);
    zero_kernel<<<SZ_OUT1 / 1024, 256>>>((float4*)out1);

    // layer 0
    sgemm_tf32<<<dim3(4, M0 / 128), 256>>>(x0, Wcat0, AB0, 512, 128);
    edge_agg<<<E0 / 8, 256>>>(ei0, E0, AB0, b0, out0);
    convpool_tf32<128><<<dim3(2, M0 / 128), 256>>>(out0, Wt0, bc0, x1);

    // layer 1
    sgemm_tf32<<<dim3(4, M1 / 128), 256>>>(x1, Wcat1, AB1, 512, 256);
    edge_agg<<<E1 / 8, 256>>>(ei1, E1, AB1, b1, out1);
    convpool_tf32<64><<<dim3(2, M1 / 128), 256>>>(out1, Wt1, bc1, out);
}

// round 8
// speedup vs baseline: 1.2611x; 1.2570x over previous
#include <cuda_runtime.h>
#include <cstdint>

// ---------------------------------------------------------------------------
// Encoder_35064113004946 — legacy tf32 HMMA + cp.async pipeline + CSR gather
//
// EdgeConv: cat[x_i,x_j-x_i]@W = x_i@Wt+(x_j-x_i)@Wb; fold C=A-B into weights:
//   Wcat' = [Wtop-Wbot | Wbot]  =>  GEMM0 emits [D|B], D=A-B.
//   out_d = max_s relu(D_d + b + B_s) = relu(D_d + b + max_s B_s)  (relu monotone)
//   CSR by dst (count/scan/scatter), warp-per-dst gather-max, no atomics.
// Conv1d(k=5,pad=2)+ReLU+MaxPool(2): GEMM over K=5*256 with shifted-row A
//   gather (cp.async zfill for boundaries); bias+relu+pool fused in epilogue.
// GEMMs: mma.sync.m16n8k8 tf32 (cvt.rna at fragment load), 2-stage cp.async.
// ---------------------------------------------------------------------------

#define M0 32768
#define E0 262144
#define M1 16384
#define E1 131072

// scratch layout (4-byte words)
#define OFF_X0     0
#define SZ_X0      (M0 * 128)
#define OFF_AB0    (OFF_X0 + SZ_X0)
#define SZ_AB0     (M0 * 512)
#define OFF_OUT0   (OFF_AB0 + SZ_AB0)
#define SZ_OUT0    (M0 * 256)
#define OFF_X1     (OFF_OUT0 + SZ_OUT0)
#define SZ_X1      (M1 * 256)
#define OFF_AB1    (OFF_X1 + SZ_X1)
#define SZ_AB1     (M1 * 512)
#define OFF_OUT1   (OFF_AB1 + SZ_AB1)
#define SZ_OUT1    (M1 * 256)
#define OFF_WCAT0  (OFF_OUT1 + SZ_OUT1)
#define SZ_WCAT0   (128 * 512)
#define OFF_WCAT1  (OFF_WCAT0 + SZ_WCAT0)
#define SZ_WCAT1   (256 * 512)
#define OFF_WT0    (OFF_WCAT1 + SZ_WCAT1)
#define SZ_WT      (1280 * 256)
#define OFF_WT1    (OFF_WT0 + SZ_WT)
#define OFF_CSR0   (OFF_WT1 + SZ_WT)
#define OFF_CSR1   (OFF_CSR0 + E0)
#define OFF_ROW0   (OFF_CSR1 + E1)
#define OFF_ROW1   (OFF_ROW0 + M0 + 4)
#define OFF_CNT0   (OFF_ROW1 + M1 + 4)       // cnt0,cur0,cnt1,cur1 contiguous
#define OFF_CUR0   (OFF_CNT0 + M0)
#define OFF_CNT1   (OFF_CUR0 + M0)
#define OFF_CUR1   (OFF_CNT1 + M1)
#define SZ_AUX     (2 * M0 + 2 * M1)         // 98304
#define SCRATCH_TOTAL (OFF_CNT0 + SZ_AUX)

__device__ __align__(16) unsigned g_scratch[SCRATCH_TOTAL];

// ---------------------------------------------------------------------------
__device__ __forceinline__ unsigned f2tf32(float x) {
    unsigned r;
    asm("cvt.rna.tf32.f32 %0, %1;" : "=r"(r) : "f"(x));
    return r;
}
__device__ __forceinline__ void mma_tf32(float* d, const unsigned* a, const unsigned* b) {
    asm volatile(
        "mma.sync.aligned.m16n8k8.row.col.f32.tf32.tf32.f32 "
        "{%0,%1,%2,%3}, {%4,%5,%6,%7}, {%8,%9}, {%0,%1,%2,%3};\n"
        : "+f"(d[0]), "+f"(d[1]), "+f"(d[2]), "+f"(d[3])
        : "r"(a[0]), "r"(a[1]), "r"(a[2]), "r"(a[3]), "r"(b[0]), "r"(b[1]));
}
__device__ __forceinline__ uint32_t smem_u32(const void* p) {
    uint32_t a;
    asm("{ .reg .u64 t; cvta.to.shared.u64 t, %1; cvt.u32.u64 %0, t; }"
        : "=r"(a) : "l"(p));
    return a;
}
__device__ __forceinline__ float4 max4(float4 a, float4 b) {
    return make_float4(fmaxf(a.x, b.x), fmaxf(a.y, b.y),
                       fmaxf(a.z, b.z), fmaxf(a.w, b.w));
}

// ---------------------------------------------------------------------------
// input permute: data[T,B,N,F] -> x0[(b*32+n)*128 + t, f]
__global__ void permute_in(const float* __restrict__ data, float* __restrict__ x0) {
    int idx = blockIdx.x * 256 + threadIdx.x;
    int f = idx & 127, node = idx >> 7;
    int t = node & 127, bn = node >> 7;
    int b = bn >> 5, n = bn & 31;
    x0[idx] = data[(((t * 8 + b) * 32 + n) << 7) + f];
}

// ---------------------------------------------------------------------------
// Wcat' = [Wtop-Wbot | Wbot] as [K,512] row-major; Wt[(k*256+i)*256+o]=Wc[o,i,k]
__global__ void prep_weights(const float* __restrict__ W0, const float* __restrict__ W1,
                             const float* __restrict__ Wc0, const float* __restrict__ Wc1,
                             float* __restrict__ Wcat0, float* __restrict__ Wcat1,
                             float* __restrict__ Wt0, float* __restrict__ Wt1) {
    int idx = blockIdx.x * 256 + threadIdx.x;
    if (idx < 65536) {                     // Wcat0: 128 x 512
        int f = idx >> 9, h = idx & 511;
        Wcat0[idx] = (h < 256) ? W0[f * 256 + h] - W0[(128 + f) * 256 + h]
                               : W0[(128 + f) * 256 + (h - 256)];
        return;
    }
    idx -= 65536;
    if (idx < 131072) {                    // Wcat1: 256 x 512
        int i = idx >> 9, h = idx & 511;
        Wcat1[idx] = (h < 256) ? W1[i * 256 + h] - W1[(256 + i) * 256 + h]
                               : W1[(256 + i) * 256 + (h - 256)];
        return;
    }
    idx -= 131072;
    if (idx < 327680) {                    // Wt0: 1280 x 256
        int kk = idx >> 8, o = idx & 255;
        int k = kk >> 8, i = kk & 255;
        Wt0[idx] = Wc0[(o * 256 + i) * 5 + k];
        return;
    }
    idx -= 327680;
    if (idx < 327680) {
        int kk = idx >> 8, o = idx & 255;
        int k = kk >> 8, i = kk & 255;
        Wt1[idx] = Wc1[(o * 256 + i) * 5 + k];
    }
}

// ---------------------------------------------------------------------------
__global__ void zero_aux(uint4* __restrict__ p) {
    p[blockIdx.x * 256 + threadIdx.x] = make_uint4(0, 0, 0, 0);
}

// ---------------------------------------------------------------------------
// CSR build: count -> scan (1 block) -> scatter
__global__ void count_edges(const int* __restrict__ ei, int E, int* __restrict__ cnt) {
    int e = blockIdx.x * 256 + threadIdx.x;
    if (e < E) atomicAdd(cnt + __ldg(ei + E + e), 1);
}

__global__ void scan_counts(const int* __restrict__ cnt, int* __restrict__ row, int n) {
    __shared__ int part[1024];
    int tid = threadIdx.x;
    int per = n >> 10;
    int base = tid * per;
    int s = 0;
    for (int i = 0; i < per; i++) s += cnt[base + i];
    part[tid] = s;
    __syncthreads();
    for (int off = 1; off < 1024; off <<= 1) {
        int v = (tid >= off) ? part[tid - off] : 0;
        __syncthreads();
        part[tid] += v;
        __syncthreads();
    }
    int excl = (tid == 0) ? 0 : part[tid - 1];
    for (int i = 0; i < per; i++) {
        int c = cnt[base + i];
        row[base + i] = excl;
        excl += c;
    }
    if (tid == 1023) row[n] = excl;
}

__global__ void scatter_edges(const int* __restrict__ ei, int E,
                              const int* __restrict__ row, int* __restrict__ cur,
                              int* __restrict__ csr) {
    int e = blockIdx.x * 256 + threadIdx.x;
    if (e >= E) return;
    int dst = __ldg(ei + E + e);
    int pos = __ldg(row + dst) + atomicAdd(cur + dst, 1);
    csr[pos] = __ldg(ei + e);
}

// ---------------------------------------------------------------------------
// warp-per-dst gather: out[d] = relu(D[d] + bias + max_{s in csr[d]} B[s]); 0 if empty
__global__ void gather_max(const int* __restrict__ row, const int* __restrict__ csr,
                           const float* __restrict__ AB, const float* __restrict__ bias,
                           float* __restrict__ out, int nodes) {
    int d = (blockIdx.x * 256 + threadIdx.x) >> 5;
    if (d >= nodes) return;
    int lane = threadIdx.x & 31;
    int s0 = __ldg(row + d), s1 = __ldg(row + d + 1);
    const float NEG = -3.4e38f;
    float4 m0 = make_float4(NEG, NEG, NEG, NEG), m1 = m0;
    int e = s0;
    for (; e + 1 < s1; e += 2) {
        int sa = __ldg(csr + e), sb = __ldg(csr + e + 1);
        const float4* Ba = (const float4*)(AB + (size_t)sa * 512 + 256);
        const float4* Bb = (const float4*)(AB + (size_t)sb * 512 + 256);
        float4 a0 = __ldg(Ba + lane), a1 = __ldg(Ba + lane + 32);
        float4 b0 = __ldg(Bb + lane), b1 = __ldg(Bb + lane + 32);
        m0 = max4(m0, max4(a0, b0));
        m1 = max4(m1, max4(a1, b1));
    }
    if (e < s1) {
        int sa = __ldg(csr + e);
        const float4* Ba = (const float4*)(AB + (size_t)sa * 512 + 256);
        m0 = max4(m0, __ldg(Ba + lane));
        m1 = max4(m1, __ldg(Ba + lane + 32));
    }
    float4* O = (float4*)(out + (size_t)d * 256);
    if (s0 == s1) {
        O[lane] = make_float4(0.f, 0.f, 0.f, 0.f);
        O[lane + 32] = make_float4(0.f, 0.f, 0.f, 0.f);
        return;
    }
    const float4* D = (const float4*)(AB + (size_t)d * 512);
    float4 d0 = __ldg(D + lane), d1 = __ldg(D + lane + 32);
    float4 b0 = __ldg((const float4*)bias + lane), b1 = __ldg((const float4*)bias + lane + 32);
    O[lane] = make_float4(fmaxf(d0.x + b0.x + m0.x, 0.f), fmaxf(d0.y + b0.y + m0.y, 0.f),
                          fmaxf(d0.z + b0.z + m0.z, 0.f), fmaxf(d0.w + b0.w + m0.w, 0.f));
    O[lane + 32] = make_float4(fmaxf(d1.x + b1.x + m1.x, 0.f), fmaxf(d1.y + b1.y + m1.y, 0.f),
                               fmaxf(d1.z + b1.z + m1.z, 0.f), fmaxf(d1.w + b1.w + m1.w, 0.f));
}

// ---------------------------------------------------------------------------
// tf32 HMMA GEMM, block tile 128x128, 8 warps (warp 32x64), 2-stage cp.async.
// CONV=0: C[M,N] = A[M,K] @ Bw[K,N]
// CONV=1: A is conv-expanded view of X[M,256] (kk=k*256+i -> X[rm+k-2][i],
//         guarded per-sequence of length L); epilogue bias+relu+maxpool(2).
template <int CONV, int L>
__global__ __launch_bounds__(256, 2)
void mma_gemm(const float* __restrict__ A, const float* __restrict__ Bw,
              const float* __restrict__ bias, float* __restrict__ C,
              int N, int K, int astride) {
    __shared__ float sA[2][128][20];   // rows padded 16->20: frag LDS conflict-free
    __shared__ float sB[2][16][136];   // rows padded 128->136
    int tid = threadIdx.x;
    int lane = tid & 31, wid = tid >> 5;
    int wm = wid & 3, wn = wid >> 2;
    int gid = lane >> 2, tg = lane & 3;
    int bm = blockIdx.y * 128, bn = blockIdx.x * 128;
    float acc[2][8][4] = {};

    auto stage = [&](int buf, int k0) {
        int ksh = 0, acol0 = k0;
        if constexpr (CONV) { ksh = (k0 >> 8) - 2; acol0 = k0 & 255; }
#pragma unroll
        for (int h = 0; h < 2; h++) {
            int q = tid + h * 256;          // 512 chunks: A tile 128x16 fp32
            int r = q >> 2, quad = q & 3;
            uint32_t dst = smem_u32(&sA[buf][r][quad * 4]);
            const float* src;
            int sz = 16;
            if constexpr (CONV) {
                int rm = bm + r, srow = rm + ksh;
                if (srow < 0 || (srow / L) != (rm / L)) { srow = rm; sz = 0; }
                src = A + (size_t)srow * astride + acol0 + quad * 4;
            } else {
                src = A + (size_t)(bm + r) * astride + k0 + quad * 4;
            }
            asm volatile("cp.async.ca.shared.global [%0], [%1], 16, %2;"
                         :: "r"(dst), "l"(src), "r"(sz) : "memory");
        }
#pragma unroll
        for (int h = 0; h < 2; h++) {
            int q = tid + h * 256;          // 512 chunks: B tile 16x128 fp32
            int r = q >> 5, quad = q & 31;
            uint32_t dst = smem_u32(&sB[buf][r][quad * 4]);
            const float* src = Bw + (size_t)(k0 + r) * N + bn + quad * 4;
            asm volatile("cp.async.ca.shared.global [%0], [%1], 16;"
                         :: "r"(dst), "l"(src) : "memory");
        }
        asm volatile("cp.async.commit_group;" ::: "memory");
    };

    stage(0, 0);
    int KT = K >> 4;
    for (int kt = 0; kt < KT; kt++) {
        int buf = kt & 1;
        if (kt + 1 < KT) {
            stage(buf ^ 1, (kt + 1) << 4);
            asm volatile("cp.async.wait_group 1;" ::: "memory");
        } else {
            asm volatile("cp.async.wait_group 0;" ::: "memory");
        }
        __syncthreads();
#pragma unroll
        for (int kk = 0; kk < 16; kk += 8) {
            unsigned a[2][4], b[8][2];
#pragma unroll
            for (int mi = 0; mi < 2; mi++) {
                int m0 = wm * 32 + mi * 16 + gid;
                a[mi][0] = f2tf32(sA[buf][m0][kk + tg]);
                a[mi][1] = f2tf32(sA[buf][m0 + 8][kk + tg]);
                a[mi][2] = f2tf32(sA[buf][m0][kk + tg + 4]);
                a[mi][3] = f2tf32(sA[buf][m0 + 8][kk + tg + 4]);
            }
#pragma unroll
            for (int ni = 0; ni < 8; ni++) {
                int n0 = wn * 64 + ni * 8 + gid;
                b[ni][0] = f2tf32(sB[buf][kk + tg][n0]);
                b[ni][1] = f2tf32(sB[buf][kk + tg + 4][n0]);
            }
#pragma unroll
            for (int mi = 0; mi < 2; mi++)
#pragma unroll
                for (int ni = 0; ni < 8; ni++)
                    mma_tf32(acc[mi][ni], a[mi], b[ni]);
        }
        __syncthreads();
    }

    if constexpr (!CONV) {
#pragma unroll
        for (int mi = 0; mi < 2; mi++) {
            int r0 = bm + wm * 32 + mi * 16 + gid;
#pragma unroll
            for (int ni = 0; ni < 8; ni++) {
                int c0 = bn + wn * 64 + ni * 8 + tg * 2;
                *(float2*)(C + (size_t)r0 * N + c0) = make_float2(acc[mi][ni][0], acc[mi][ni][1]);
                *(float2*)(C + (size_t)(r0 + 8) * N + c0) = make_float2(acc[mi][ni][2], acc[mi][ni][3]);
            }
        }
    } else {
        // bias + relu + maxpool(2): partner row gid^1 lives in lane^4
        bool wr = (gid & 1) == 0;
#pragma unroll
        for (int mi = 0; mi < 2; mi++) {
            int rbase = bm + wm * 32 + mi * 16 + gid;
#pragma unroll
            for (int ni = 0; ni < 8; ni++) {
                int c0 = bn + wn * 64 + ni * 8 + tg * 2;
                float b0 = bias[c0], b1 = bias[c0 + 1];
                float u0 = fmaxf(acc[mi][ni][0] + b0, 0.f);
                float u1 = fmaxf(acc[mi][ni][1] + b1, 0.f);
                float u2 = fmaxf(acc[mi][ni][2] + b0, 0.f);
                float u3 = fmaxf(acc[mi][ni][3] + b1, 0.f);
                float p0 = fmaxf(u0, __shfl_xor_sync(0xffffffffu, u0, 4));
                float p1 = fmaxf(u1, __shfl_xor_sync(0xffffffffu, u1, 4));
                float p2 = fmaxf(u2, __shfl_xor_sync(0xffffffffu, u2, 4));
                float p3 = fmaxf(u3, __shfl_xor_sync(0xffffffffu, u3, 4));
                if (wr) {
                    *(float2*)(C + (size_t)(rbase >> 1) * 256 + c0) = make_float2(p0, p1);
                    *(float2*)(C + (size_t)((rbase + 8) >> 1) * 256 + c0) = make_float2(p2, p3);
                }
            }
        }
    }
}

// ---------------------------------------------------------------------------
extern "C" void kernel_launch(void* const* d_in, const int* in_sizes, int n_in,
                              void* d_out, int out_size) {
    const float* data = (const float*)d_in[0];
    const int*   ei0  = (const int*)d_in[2];
    const int*   ei1  = (const int*)d_in[3];
    const float* W0   = (const float*)d_in[4];
    const float* b0   = (const float*)d_in[5];
    const float* Wc0  = (const float*)d_in[6];
    const float* bc0  = (const float*)d_in[7];
    const float* W1   = (const float*)d_in[8];
    const float* b1   = (const float*)d_in[9];
    const float* Wc1  = (const float*)d_in[10];
    const float* bc1  = (const float*)d_in[11];
    float* out = (float*)d_out;

    void* sp = nullptr;
    cudaGetSymbolAddress(&sp, g_scratch);
    float* S     = (float*)sp;
    float* x0    = S + OFF_X0;
    float* AB0   = S + OFF_AB0;
    float* out0  = S + OFF_OUT0;
    float* x1    = S + OFF_X1;
    float* AB1   = S + OFF_AB1;
    float* out1  = S + OFF_OUT1;
    float* Wcat0 = S + OFF_WCAT0;
    float* Wcat1 = S + OFF_WCAT1;
    float* Wt0   = S + OFF_WT0;
    float* Wt1   = S + OFF_WT1;
    int* csr0 = (int*)(S + OFF_CSR0);
    int* csr1 = (int*)(S + OFF_CSR1);
    int* row0 = (int*)(S + OFF_ROW0);
    int* row1 = (int*)(S + OFF_ROW1);
    int* cnt0 = (int*)(S + OFF_CNT0);
    int* cur0 = (int*)(S + OFF_CUR0);
    int* cnt1 = (int*)(S + OFF_CNT1);
    int* cur1 = (int*)(S + OFF_CUR1);

    prep_weights<<<3328, 256>>>(W0, W1, Wc0, Wc1, Wcat0, Wcat1, Wt0, Wt1);
    permute_in<<<(M0 * 128) / 256, 256>>>(data, x0);
    zero_aux<<<SZ_AUX / 1024, 256>>>((uint4*)cnt0);

    // CSR builds (independent of GEMMs)
    count_edges<<<E0 / 256, 256>>>(ei0, E0, cnt0);
    count_edges<<<E1 / 256, 256>>>(ei1, E1, cnt1);
    scan_counts<<<1, 1024>>>(cnt0, row0, M0);
    scan_counts<<<1, 1024>>>(cnt1, row1, M1);
    scatter_edges<<<E0 / 256, 256>>>(ei0, E0, row0, cur0, csr0);
    scatter_edges<<<E1 / 256, 256>>>(ei1, E1, row1, cur1, csr1);

    // layer 0
    mma_gemm<0, 1><<<dim3(4, M0 / 128), 256>>>(x0, Wcat0, nullptr, AB0, 512, 128, 128);
    gather_max<<<M0 / 8, 256>>>(row0, csr0, AB0, b0, out0, M0);
    mma_gemm<1, 128><<<dim3(2, M0 / 128), 256>>>(out0, Wt0, bc0, x1, 256, 1280, 256);

    // layer 1
    mma_gemm<0, 1><<<dim3(4, M1 / 128), 256>>>(x1, Wcat1, nullptr, AB1, 512, 256, 256);
    gather_max<<<M1 / 8, 256>>>(row1, csr1, AB1, b1, out1, M1);
    mma_gemm<1, 64><<<dim3(2, M1 / 128), 256>>>(out1, Wt1, bc1, out, 256, 1280, 256);
}

// round 13
// speedup vs baseline: 1.5480x; 1.2275x over previous
#include <cuda_runtime.h>
#include <cstdint>

// ---------------------------------------------------------------------------
// Encoder_35064113004946 — tf32 HMMA + 3-stage cp.async + bucket-CSR gather
//
// EdgeConv: cat[x_i,x_j-x_i]@W = x_i@Wt+(x_j-x_i)@Wb; fold C=A-B into weights:
//   Wcat' = [Wtop-Wbot | Wbot]  =>  GEMM0 emits [D|B], D=A-B.
//   out_d = max_s relu(D_d + b + B_s) = relu(D_d + b + max_s B_s)
//   Edges: fixed-cap (64) buckets via atomicAdd slot (deg ~Poisson(8); P(>64)
//   ~1e-35; max is order-invariant => deterministic). Warp-per-dst gather-max.
// Conv1d(k=5,pad=2)+ReLU+MaxPool(2): GEMM over K=5*256, shifted-row cp.async
//   zfill gather; bias+relu+pool fused in epilogue.
// GEMMs: mma.sync.m16n8k8 tf32; ALL GEMM inputs pre-rounded to tf32 at their
//   producers (idempotent cvt.rna) so the mainloop does raw LDS only.
// ---------------------------------------------------------------------------

#define M0 32768
#define E0 262144
#define M1 16384
#define E1 131072
#define CAP 64

// scratch layout (4-byte words)
#define OFF_X0     0
#define SZ_X0      (M0 * 128)
#define OFF_AB0    (OFF_X0 + SZ_X0)
#define SZ_AB0     (M0 * 512)
#define OFF_OUT0   (OFF_AB0 + SZ_AB0)
#define SZ_OUT0    (M0 * 256)
#define OFF_X1     (OFF_OUT0 + SZ_OUT0)
#define SZ_X1      (M1 * 256)
#define OFF_AB1    (OFF_X1 + SZ_X1)
#define SZ_AB1     (M1 * 512)
#define OFF_OUT1   (OFF_AB1 + SZ_AB1)
#define SZ_OUT1    (M1 * 256)
#define OFF_WCAT0  (OFF_OUT1 + SZ_OUT1)
#define SZ_WCAT0   (128 * 512)
#define OFF_WCAT1  (OFF_WCAT0 + SZ_WCAT0)
#define SZ_WCAT1   (256 * 512)
#define OFF_WT0    (OFF_WCAT1 + SZ_WCAT1)
#define SZ_WT      (1280 * 256)
#define OFF_WT1    (OFF_WT0 + SZ_WT)
#define OFF_BKT0   (OFF_WT1 + SZ_WT)
#define OFF_BKT1   (OFF_BKT0 + M0 * CAP)
#define OFF_CNT0   (OFF_BKT1 + M1 * CAP)
#define OFF_CNT1   (OFF_CNT0 + M0)
#define SCRATCH_TOTAL (OFF_CNT1 + M1)

__device__ __align__(16) unsigned g_scratch[SCRATCH_TOTAL];

// ---------------------------------------------------------------------------
__device__ __forceinline__ float rndtf32(float x) {
    unsigned r;
    asm("cvt.rna.tf32.f32 %0, %1;" : "=r"(r) : "f"(x));
    return __uint_as_float(r);
}
__device__ __forceinline__ void mma_tf32(float* d, const unsigned* a, const unsigned* b) {
    asm volatile(
        "mma.sync.aligned.m16n8k8.row.col.f32.tf32.tf32.f32 "
        "{%0,%1,%2,%3}, {%4,%5,%6,%7}, {%8,%9}, {%0,%1,%2,%3};\n"
        : "+f"(d[0]), "+f"(d[1]), "+f"(d[2]), "+f"(d[3])
        : "r"(a[0]), "r"(a[1]), "r"(a[2]), "r"(a[3]), "r"(b[0]), "r"(b[1]));
}
__device__ __forceinline__ uint32_t smem_u32(const void* p) {
    uint32_t a;
    asm("{ .reg .u64 t; cvta.to.shared.u64 t, %1; cvt.u32.u64 %0, t; }"
        : "=r"(a) : "l"(p));
    return a;
}
__device__ __forceinline__ float4 max4(float4 a, float4 b) {
    return make_float4(fmaxf(a.x, b.x), fmaxf(a.y, b.y),
                       fmaxf(a.z, b.z), fmaxf(a.w, b.w));
}

// ---------------------------------------------------------------------------
// input permute: data[T,B,N,F] -> x0[(b*32+n)*128 + t, f], tf32-rounded
__global__ void permute_in(const float* __restrict__ data, float* __restrict__ x0) {
    int idx = blockIdx.x * 256 + threadIdx.x;
    int f = idx & 127, node = idx >> 7;
    int t = node & 127, bn = node >> 7;
    int b = bn >> 5, n = bn & 31;
    x0[idx] = rndtf32(data[(((t * 8 + b) * 32 + n) << 7) + f]);
}

// ---------------------------------------------------------------------------
// Wcat' = [Wtop-Wbot | Wbot] as [K,512]; Wt[(k*256+i)*256+o]=Wc[o,i,k]; tf32-rounded
__global__ void prep_weights(const float* __restrict__ W0, const float* __restrict__ W1,
                             const float* __restrict__ Wc0, const float* __restrict__ Wc1,
                             float* __restrict__ Wcat0, float* __restrict__ Wcat1,
                             float* __restrict__ Wt0, float* __restrict__ Wt1) {
    int idx = blockIdx.x * 256 + threadIdx.x;
    if (idx < 65536) {
        int f = idx >> 9, h = idx & 511;
        Wcat0[idx] = rndtf32((h < 256) ? W0[f * 256 + h] - W0[(128 + f) * 256 + h]
                                       : W0[(128 + f) * 256 + (h - 256)]);
        return;
    }
    idx -= 65536;
    if (idx < 131072) {
        int i = idx >> 9, h = idx & 511;
        Wcat1[idx] = rndtf32((h < 256) ? W1[i * 256 + h] - W1[(256 + i) * 256 + h]
                                       : W1[(256 + i) * 256 + (h - 256)]);
        return;
    }
    idx -= 131072;
    if (idx < 327680) {
        int kk = idx >> 8, o = idx & 255;
        int k = kk >> 8, i = kk & 255;
        Wt0[idx] = rndtf32(Wc0[(o * 256 + i) * 5 + k]);
        return;
    }
    idx -= 327680;
    if (idx < 327680) {
        int kk = idx >> 8, o = idx & 255;
        int k = kk >> 8, i = kk & 255;
        Wt1[idx] = rndtf32(Wc1[(o * 256 + i) * 5 + k]);
    }
}

// ---------------------------------------------------------------------------
__global__ void zero_cnt(int* __restrict__ p) {
    p[blockIdx.x * 256 + threadIdx.x] = 0;
}

// bucket fill: slot per (dst) via atomicAdd; max later is order-invariant
__global__ void fill_edges(const int* __restrict__ ei, int E,
                           int* __restrict__ cnt, int* __restrict__ bkt) {
    int e = blockIdx.x * 256 + threadIdx.x;
    if (e >= E) return;
    int dst = __ldg(ei + E + e);
    int slot = atomicAdd(cnt + dst, 1);
    if (slot < CAP) bkt[(size_t)dst * CAP + slot] = __ldg(ei + e);
}

// ---------------------------------------------------------------------------
// warp-per-dst: out[d] = relu(D[d]+bias+max_s B[s]) (tf32-rounded); 0 if empty
__global__ void gather_max(const int* __restrict__ cnt, const int* __restrict__ bkt,
                           const float* __restrict__ AB, const float* __restrict__ bias,
                           float* __restrict__ out, int nodes) {
    int d = (blockIdx.x * 256 + threadIdx.x) >> 5;
    if (d >= nodes) return;
    int lane = threadIdx.x & 31;
    int n = __ldg(cnt + d);
    n = n < CAP ? n : CAP;
    float4* O = (float4*)(out + (size_t)d * 256);
    if (n == 0) {
        O[lane] = make_float4(0.f, 0.f, 0.f, 0.f);
        O[lane + 32] = make_float4(0.f, 0.f, 0.f, 0.f);
        return;
    }
    const int* bp = bkt + (size_t)d * CAP;
    const float NEG = -3.4e38f;
    float4 m0 = make_float4(NEG, NEG, NEG, NEG), m1 = m0;
    int e = 0;
    for (; e + 1 < n; e += 2) {
        int sa = __ldg(bp + e), sb = __ldg(bp + e + 1);
        const float4* Ba = (const float4*)(AB + (size_t)sa * 512 + 256);
        const float4* Bb = (const float4*)(AB + (size_t)sb * 512 + 256);
        m0 = max4(m0, max4(__ldg(Ba + lane), __ldg(Bb + lane)));
        m1 = max4(m1, max4(__ldg(Ba + lane + 32), __ldg(Bb + lane + 32)));
    }
    if (e < n) {
        int sa = __ldg(bp + e);
        const float4* Ba = (const float4*)(AB + (size_t)sa * 512 + 256);
        m0 = max4(m0, __ldg(Ba + lane));
        m1 = max4(m1, __ldg(Ba + lane + 32));
    }
    const float4* D = (const float4*)(AB + (size_t)d * 512);
    float4 d0 = __ldg(D + lane), d1 = __ldg(D + lane + 32);
    float4 b0 = __ldg((const float4*)bias + lane), b1 = __ldg((const float4*)bias + lane + 32);
    O[lane] = make_float4(rndtf32(fmaxf(d0.x + b0.x + m0.x, 0.f)),
                          rndtf32(fmaxf(d0.y + b0.y + m0.y, 0.f)),
                          rndtf32(fmaxf(d0.z + b0.z + m0.z, 0.f)),
                          rndtf32(fmaxf(d0.w + b0.w + m0.w, 0.f)));
    O[lane + 32] = make_float4(rndtf32(fmaxf(d1.x + b1.x + m1.x, 0.f)),
                               rndtf32(fmaxf(d1.y + b1.y + m1.y, 0.f)),
                               rndtf32(fmaxf(d1.z + b1.z + m1.z, 0.f)),
                               rndtf32(fmaxf(d1.w + b1.w + m1.w, 0.f)));
}

// ---------------------------------------------------------------------------
// tf32 HMMA GEMM, block 128x128, 8 warps (warp 32x64), 3-stage cp.async,
// one __syncthreads per k-tile. Inputs pre-rounded tf32 -> raw LDS in loop.
// CONV=0: C = A[M,K] @ Bw[K,N].  CONV=1: conv-expanded A + bias/relu/pool
// epilogue (FIN=0 rounds output for next GEMM; FIN=1 leaves fp32).
#define SA_W 20
#define SB_W 136
#define SA_SZ (128 * SA_W)
#define SB_SZ (16 * SB_W)
#define GEMM_SMEM ((3 * SA_SZ + 3 * SB_SZ) * 4)

template <int CONV, int L, int FIN>
__global__ __launch_bounds__(256, 2)
void mma_gemm(const float* __restrict__ A, const float* __restrict__ Bw,
              const float* __restrict__ bias, float* __restrict__ C,
              int N, int K, int astride) {
    extern __shared__ float smem[];
    float* sA = smem;                  // [3][128][SA_W]
    float* sB = smem + 3 * SA_SZ;      // [3][16][SB_W]
    int tid = threadIdx.x;
    int lane = tid & 31, wid = tid >> 5;
    int wm = wid & 3, wn = wid >> 2;
    int gid = lane >> 2, tg = lane & 3;
    int bm = blockIdx.y * 128, bn = blockIdx.x * 128;
    float acc[2][8][4] = {};

    auto stage = [&](int buf, int k0) {
        float* bA = sA + buf * SA_SZ;
        float* bB = sB + buf * SB_SZ;
        int ksh = 0, acol0 = k0;
        if constexpr (CONV) { ksh = (k0 >> 8) - 2; acol0 = k0 & 255; }
#pragma unroll
        for (int h = 0; h < 2; h++) {
            int q = tid + h * 256;
            int r = q >> 2, quad = q & 3;
            uint32_t dst = smem_u32(bA + r * SA_W + quad * 4);
            const float* src;
            int sz = 16;
            if constexpr (CONV) {
                int rm = bm + r, srow = rm + ksh;
                if (srow < 0 || (srow / L) != (rm / L)) { srow = rm; sz = 0; }
                src = A + (size_t)srow * astride + acol0 + quad * 4;
            } else {
                src = A + (size_t)(bm + r) * astride + k0 + quad * 4;
            }
            asm volatile("cp.async.ca.shared.global [%0], [%1], 16, %2;"
                         :: "r"(dst), "l"(src), "r"(sz) : "memory");
        }
#pragma unroll
        for (int h = 0; h < 2; h++) {
            int q = tid + h * 256;
            int r = q >> 5, quad = q & 31;
            uint32_t dst = smem_u32(bB + r * SB_W + quad * 4);
            const float* src = Bw + (size_t)(k0 + r) * N + bn + quad * 4;
            asm volatile("cp.async.ca.shared.global [%0], [%1], 16;"
                         :: "r"(dst), "l"(src) : "memory");
        }
        asm volatile("cp.async.commit_group;" ::: "memory");
    };

    int KT = K >> 4;
    stage(0, 0);
    stage(1, 16);
    for (int kt = 0; kt < KT; kt++) {
        if (kt + 1 < KT)
            asm volatile("cp.async.wait_group 1;" ::: "memory");
        else
            asm volatile("cp.async.wait_group 0;" ::: "memory");
        __syncthreads();
        int buf = kt % 3;
        const float* bA = sA + buf * SA_SZ;
        const float* bB = sB + buf * SB_SZ;
#pragma unroll
        for (int kk = 0; kk < 16; kk += 8) {
            unsigned a[2][4], b[8][2];
#pragma unroll
            for (int mi = 0; mi < 2; mi++) {
                int m0 = wm * 32 + mi * 16 + gid;
                a[mi][0] = __float_as_uint(bA[m0 * SA_W + kk + tg]);
                a[mi][1] = __float_as_uint(bA[(m0 + 8) * SA_W + kk + tg]);
                a[mi][2] = __float_as_uint(bA[m0 * SA_W + kk + tg + 4]);
                a[mi][3] = __float_as_uint(bA[(m0 + 8) * SA_W + kk + tg + 4]);
            }
#pragma unroll
            for (int ni = 0; ni < 8; ni++) {
                int n0 = wn * 64 + ni * 8 + gid;
                b[ni][0] = __float_as_uint(bB[(kk + tg) * SB_W + n0]);
                b[ni][1] = __float_as_uint(bB[(kk + tg + 4) * SB_W + n0]);
            }
#pragma unroll
            for (int mi = 0; mi < 2; mi++)
#pragma unroll
                for (int ni = 0; ni < 8; ni++)
                    mma_tf32(acc[mi][ni], a[mi], b[ni]);
        }
        if (kt + 2 < KT) stage((kt + 2) % 3, (kt + 2) << 4);
    }

    if constexpr (!CONV) {
#pragma unroll
        for (int mi = 0; mi < 2; mi++) {
            int r0 = bm + wm * 32 + mi * 16 + gid;
#pragma unroll
            for (int ni = 0; ni < 8; ni++) {
                int c0 = bn + wn * 64 + ni * 8 + tg * 2;
                *(float2*)(C + (size_t)r0 * N + c0) = make_float2(acc[mi][ni][0], acc[mi][ni][1]);
                *(float2*)(C + (size_t)(r0 + 8) * N + c0) = make_float2(acc[mi][ni][2], acc[mi][ni][3]);
            }
        }
    } else {
        bool wr = (gid & 1) == 0;
#pragma unroll
        for (int mi = 0; mi < 2; mi++) {
            int rbase = bm + wm * 32 + mi * 16 + gid;
#pragma unroll
            for (int ni = 0; ni < 8; ni++) {
                int c0 = bn + wn * 64 + ni * 8 + tg * 2;
                float b0 = bias[c0], b1 = bias[c0 + 1];
                float u0 = fmaxf(acc[mi][ni][0] + b0, 0.f);
                float u1 = fmaxf(acc[mi][ni][1] + b1, 0.f);
                float u2 = fmaxf(acc[mi][ni][2] + b0, 0.f);
                float u3 = fmaxf(acc[mi][ni][3] + b1, 0.f);
                float p0 = fmaxf(u0, __shfl_xor_sync(0xffffffffu, u0, 4));
                float p1 = fmaxf(u1, __shfl_xor_sync(0xffffffffu, u1, 4));
                float p2 = fmaxf(u2, __shfl_xor_sync(0xffffffffu, u2, 4));
                float p3 = fmaxf(u3, __shfl_xor_sync(0xffffffffu, u3, 4));
                if constexpr (!FIN) {
                    p0 = rndtf32(p0); p1 = rndtf32(p1);
                    p2 = rndtf32(p2); p3 = rndtf32(p3);
                }
                if (wr) {
                    *(float2*)(C + (size_t)(rbase >> 1) * 256 + c0) = make_float2(p0, p1);
                    *(float2*)(C + (size_t)((rbase + 8) >> 1) * 256 + c0) = make_float2(p2, p3);
                }
            }
        }
    }
}

// ---------------------------------------------------------------------------
extern "C" void kernel_launch(void* const* d_in, const int* in_sizes, int n_in,
                              void* d_out, int out_size) {
    const float* data = (const float*)d_in[0];
    const int*   ei0  = (const int*)d_in[2];
    const int*   ei1  = (const int*)d_in[3];
    const float* W0   = (const float*)d_in[4];
    const float* b0   = (const float*)d_in[5];
    const float* Wc0  = (const float*)d_in[6];
    const float* bc0  = (const float*)d_in[7];
    const float* W1   = (const float*)d_in[8];
    const float* b1   = (const float*)d_in[9];
    const float* Wc1  = (const float*)d_in[10];
    const float* bc1  = (const float*)d_in[11];
    float* out = (float*)d_out;

    void* sp = nullptr;
    cudaGetSymbolAddress(&sp, g_scratch);
    float* S     = (float*)sp;
    float* x0    = S + OFF_X0;
    float* AB0   = S + OFF_AB0;
    float* out0  = S + OFF_OUT0;
    float* x1    = S + OFF_X1;
    float* AB1   = S + OFF_AB1;
    float* out1  = S + OFF_OUT1;
    float* Wcat0 = S + OFF_WCAT0;
    float* Wcat1 = S + OFF_WCAT1;
    float* Wt0   = S + OFF_WT0;
    float* Wt1   = S + OFF_WT1;
    int* bkt0 = (int*)(S + OFF_BKT0);
    int* bkt1 = (int*)(S + OFF_BKT1);
    int* cnt0 = (int*)(S + OFF_CNT0);
    int* cnt1 = (int*)(S + OFF_CNT1);

    static bool attr_done = false;
    if (!attr_done) {
        cudaFuncSetAttribute(mma_gemm<0, 1, 0>, cudaFuncAttributeMaxDynamicSharedMemorySize, GEMM_SMEM);
        cudaFuncSetAttribute(mma_gemm<1, 128, 0>, cudaFuncAttributeMaxDynamicSharedMemorySize, GEMM_SMEM);
        cudaFuncSetAttribute(mma_gemm<1, 64, 1>, cudaFuncAttributeMaxDynamicSharedMemorySize, GEMM_SMEM);
        attr_done = true;
    }

    prep_weights<<<3328, 256>>>(W0, W1, Wc0, Wc1, Wcat0, Wcat1, Wt0, Wt1);
    permute_in<<<(M0 * 128) / 256, 256>>>(data, x0);
    zero_cnt<<<(M0 + M1) / 256, 256>>>(cnt0);   // cnt0,cnt1 contiguous

    fill_edges<<<E0 / 256, 256>>>(ei0, E0, cnt0, bkt0);
    fill_edges<<<E1 / 256, 256>>>(ei1, E1, cnt1, bkt1);

    // layer 0
    mma_gemm<0, 1, 0><<<dim3(4, M0 / 128), 256, GEMM_SMEM>>>(x0, Wcat0, nullptr, AB0, 512, 128, 128);
    gather_max<<<M0 / 8, 256>>>(cnt0, bkt0, AB0, b0, out0, M0);
    mma_gemm<1, 128, 0><<<dim3(2, M0 / 128), 256, GEMM_SMEM>>>(out0, Wt0, bc0, x1, 256, 1280, 256);

    // layer 1
    mma_gemm<0, 1, 0><<<dim3(4, M1 / 128), 256, GEMM_SMEM>>>(x1, Wcat1, nullptr, AB1, 512, 256, 256);
    gather_max<<<M1 / 8, 256>>>(cnt1, bkt1, AB1, b1, out1, M1);
    mma_gemm<1, 64, 1><<<dim3(2, M1 / 128), 256, GEMM_SMEM>>>(out1, Wt1, bc1, out, 256, 1280, 256);
}

// round 14
// speedup vs baseline: 1.7493x; 1.1300x over previous
#include <cuda_runtime.h>
#include <cstdint>

// ---------------------------------------------------------------------------
// Encoder_35064113004946 — tf32 HMMA + ldmatrix frags + cp.async + bucket CSR
//
// EdgeConv: cat[x_i,x_j-x_i]@W = x_i@Wt+(x_j-x_i)@Wb; fold C=A-B into weights:
//   Wcat' = [Wtop-Wbot | Wbot]  =>  GEMM0 emits [D|B], D=A-B.
//   out_d = max_s relu(D_d + b + B_s) = relu(D_d + b + max_s B_s)
//   Edges: fixed-cap(64) buckets via atomicAdd slot (max is order-invariant).
// Conv1d(k=5,pad=2)+ReLU+MaxPool(2): GEMM over K=5*256, shifted-row cp.async
//   zfill gather; bias+relu+pool fused in epilogue.
// GEMMs: mma.sync.m16n8k8 tf32; fragments via ldmatrix.x4 (A row-major SMEM,
//   B n-major SMEM — weights pre-transposed). All GEMM inputs pre-rounded
//   to tf32 at producers, so the mainloop is LDSM+HMMA only.
// ---------------------------------------------------------------------------

#define M0 32768
#define E0 262144
#define M1 16384
#define E1 131072
#define CAP 64

// scratch layout (4-byte words)
#define OFF_X0     0
#define SZ_X0      (M0 * 128)
#define OFF_AB0    (OFF_X0 + SZ_X0)
#define SZ_AB0     (M0 * 512)
#define OFF_OUT0   (OFF_AB0 + SZ_AB0)
#define SZ_OUT0    (M0 * 256)
#define OFF_X1     (OFF_OUT0 + SZ_OUT0)
#define SZ_X1      (M1 * 256)
#define OFF_AB1    (OFF_X1 + SZ_X1)
#define SZ_AB1     (M1 * 512)
#define OFF_OUT1   (OFF_AB1 + SZ_AB1)
#define SZ_OUT1    (M1 * 256)
#define OFF_WCAT0  (OFF_OUT1 + SZ_OUT1)
#define SZ_WCAT0   (512 * 128)
#define OFF_WCAT1  (OFF_WCAT0 + SZ_WCAT0)
#define SZ_WCAT1   (512 * 256)
#define OFF_WT0    (OFF_WCAT1 + SZ_WCAT1)
#define SZ_WT      (256 * 1280)
#define OFF_WT1    (OFF_WT0 + SZ_WT)
#define OFF_BKT0   (OFF_WT1 + SZ_WT)
#define OFF_BKT1   (OFF_BKT0 + M0 * CAP)
#define OFF_CNT0   (OFF_BKT1 + M1 * CAP)
#define OFF_CNT1   (OFF_CNT0 + M0)
#define SCRATCH_TOTAL (OFF_CNT1 + M1)

__device__ __align__(16) unsigned g_scratch[SCRATCH_TOTAL];

// ---------------------------------------------------------------------------
__device__ __forceinline__ float rndtf32(float x) {
    unsigned r;
    asm("cvt.rna.tf32.f32 %0, %1;" : "=r"(r) : "f"(x));
    return __uint_as_float(r);
}
__device__ __forceinline__ void mma_tf32(float* d, const unsigned* a, const unsigned* b) {
    asm volatile(
        "mma.sync.aligned.m16n8k8.row.col.f32.tf32.tf32.f32 "
        "{%0,%1,%2,%3}, {%4,%5,%6,%7}, {%8,%9}, {%0,%1,%2,%3};\n"
        : "+f"(d[0]), "+f"(d[1]), "+f"(d[2]), "+f"(d[3])
        : "r"(a[0]), "r"(a[1]), "r"(a[2]), "r"(a[3]), "r"(b[0]), "r"(b[1]));
}
__device__ __forceinline__ void ldsm4(unsigned* r, uint32_t addr) {
    asm volatile("ldmatrix.sync.aligned.m8n8.x4.shared.b16 {%0,%1,%2,%3}, [%4];"
                 : "=r"(r[0]), "=r"(r[1]), "=r"(r[2]), "=r"(r[3]) : "r"(addr));
}
__device__ __forceinline__ uint32_t smem_u32(const void* p) {
    uint32_t a;
    asm("{ .reg .u64 t; cvta.to.shared.u64 t, %1; cvt.u32.u64 %0, t; }"
        : "=r"(a) : "l"(p));
    return a;
}
__device__ __forceinline__ float4 max4(float4 a, float4 b) {
    return make_float4(fmaxf(a.x, b.x), fmaxf(a.y, b.y),
                       fmaxf(a.z, b.z), fmaxf(a.w, b.w));
}

// ---------------------------------------------------------------------------
// input permute: data[T,B,N,F] -> x0[(b*32+n)*128 + t, f], tf32-rounded
__global__ void permute_in(const float* __restrict__ data, float* __restrict__ x0) {
    int idx = blockIdx.x * 256 + threadIdx.x;
    int f = idx & 127, node = idx >> 7;
    int t = node & 127, bn = node >> 7;
    int b = bn >> 5, n = bn & 31;
    x0[idx] = rndtf32(data[(((t * 8 + b) * 32 + n) << 7) + f]);
}

// ---------------------------------------------------------------------------
// Weights emitted N-MAJOR [N][K] (tf32-rounded):
//  WcatT: row h of 512, cols k: h<256 -> Wtop-Wbot, else Wbot
//  WtT:   row o of 256, cols kk=k*256+i: Wc[o,i,k]
__global__ void prep_weights(const float* __restrict__ W0, const float* __restrict__ W1,
                             const float* __restrict__ Wc0, const float* __restrict__ Wc1,
                             float* __restrict__ WcT0, float* __restrict__ WcT1,
                             float* __restrict__ WtT0, float* __restrict__ WtT1) {
    int idx = blockIdx.x * 256 + threadIdx.x;
    if (idx < 65536) {                       // WcT0: 512 x 128
        int h = idx >> 7, f = idx & 127;
        WcT0[idx] = rndtf32((h < 256) ? W0[f * 256 + h] - W0[(128 + f) * 256 + h]
                                      : W0[(128 + f) * 256 + (h - 256)]);
        return;
    }
    idx -= 65536;
    if (idx < 131072) {                      // WcT1: 512 x 256
        int h = idx >> 8, i = idx & 255;
        WcT1[idx] = rndtf32((h < 256) ? W1[i * 256 + h] - W1[(256 + i) * 256 + h]
                                      : W1[(256 + i) * 256 + (h - 256)]);
        return;
    }
    idx -= 131072;
    if (idx < 327680) {                      // WtT0: 256 x 1280
        int o = idx / 1280, kk = idx % 1280;
        int k = kk >> 8, i = kk & 255;
        WtT0[idx] = rndtf32(Wc0[(o * 256 + i) * 5 + k]);
        return;
    }
    idx -= 327680;
    if (idx < 327680) {
        int o = idx / 1280, kk = idx % 1280;
        int k = kk >> 8, i = kk & 255;
        WtT1[idx] = rndtf32(Wc1[(o * 256 + i) * 5 + k]);
    }
}

// ---------------------------------------------------------------------------
__global__ void zero_cnt(int* __restrict__ p) {
    p[blockIdx.x * 256 + threadIdx.x] = 0;
}

__global__ void fill_edges(const int* __restrict__ ei, int E,
                           int* __restrict__ cnt, int* __restrict__ bkt) {
    int e = blockIdx.x * 256 + threadIdx.x;
    if (e >= E) return;
    int dst = __ldg(ei + E + e);
    int slot = atomicAdd(cnt + dst, 1);
    if (slot < CAP) bkt[(size_t)dst * CAP + slot] = __ldg(ei + e);
}

// ---------------------------------------------------------------------------
// warp-per-dst: out[d] = relu(D[d]+bias+max_s B[s]) (tf32-rounded); 0 if empty
__global__ void gather_max(const int* __restrict__ cnt, const int* __restrict__ bkt,
                           const float* __restrict__ AB, const float* __restrict__ bias,
                           float* __restrict__ out, int nodes) {
    int d = (blockIdx.x * 256 + threadIdx.x) >> 5;
    if (d >= nodes) return;
    int lane = threadIdx.x & 31;
    int n = __ldg(cnt + d);
    n = n < CAP ? n : CAP;
    float4* O = (float4*)(out + (size_t)d * 256);
    if (n == 0) {
        O[lane] = make_float4(0.f, 0.f, 0.f, 0.f);
        O[lane + 32] = make_float4(0.f, 0.f, 0.f, 0.f);
        return;
    }
    const int* bp = bkt + (size_t)d * CAP;
    const float NEG = -3.4e38f;
    float4 m0 = make_float4(NEG, NEG, NEG, NEG), m1 = m0;
    int e = 0;
    for (; e + 1 < n; e += 2) {
        int sa = __ldg(bp + e), sb = __ldg(bp + e + 1);
        const float4* Ba = (const float4*)(AB + (size_t)sa * 512 + 256);
        const float4* Bb = (const float4*)(AB + (size_t)sb * 512 + 256);
        m0 = max4(m0, max4(__ldg(Ba + lane), __ldg(Bb + lane)));
        m1 = max4(m1, max4(__ldg(Ba + lane + 32), __ldg(Bb + lane + 32)));
    }
    if (e < n) {
        int sa = __ldg(bp + e);
        const float4* Ba = (const float4*)(AB + (size_t)sa * 512 + 256);
        m0 = max4(m0, __ldg(Ba + lane));
        m1 = max4(m1, __ldg(Ba + lane + 32));
    }
    const float4* D = (const float4*)(AB + (size_t)d * 512);
    float4 d0 = __ldg(D + lane), d1 = __ldg(D + lane + 32);
    float4 b0 = __ldg((const float4*)bias + lane), b1 = __ldg((const float4*)bias + lane + 32);
    O[lane] = make_float4(rndtf32(fmaxf(d0.x + b0.x + m0.x, 0.f)),
                          rndtf32(fmaxf(d0.y + b0.y + m0.y, 0.f)),
                          rndtf32(fmaxf(d0.z + b0.z + m0.z, 0.f)),
                          rndtf32(fmaxf(d0.w + b0.w + m0.w, 0.f)));
    O[lane + 32] = make_float4(rndtf32(fmaxf(d1.x + b1.x + m1.x, 0.f)),
                               rndtf32(fmaxf(d1.y + b1.y + m1.y, 0.f)),
                               rndtf32(fmaxf(d1.z + b1.z + m1.z, 0.f)),
                               rndtf32(fmaxf(d1.w + b1.w + m1.w, 0.f)));
}

// ---------------------------------------------------------------------------
// tf32 HMMA GEMM, block 128x128, 8 warps (warp 32x64), 3-stage cp.async,
// ldmatrix fragment loads. A SMEM [128 m][20], B SMEM [128 n][20] (n-major).
// CONV=0: C = A[M,K] @ BwT[N,K]^T.  CONV=1: conv-expanded A + bias/relu/pool
// epilogue (FIN=0 rounds output for next GEMM; FIN=1 leaves fp32).
#define SROW_W 20
#define SA_SZ (128 * SROW_W)
#define SB_SZ (128 * SROW_W)
#define GEMM_SMEM ((3 * SA_SZ + 3 * SB_SZ) * 4)

template <int CONV, int L, int FIN>
__global__ __launch_bounds__(256, 2)
void mma_gemm(const float* __restrict__ A, const float* __restrict__ BwT,
              const float* __restrict__ bias, float* __restrict__ C,
              int N, int K, int astride) {
    extern __shared__ float smem[];
    float* sA = smem;                  // [3][128][20]
    float* sB = smem + 3 * SA_SZ;      // [3][128][20]
    int tid = threadIdx.x;
    int lane = tid & 31, wid = tid >> 5;
    int wm = wid & 3, wn = wid >> 2;
    int gid = lane >> 2, tg = lane & 3;
    int bm = blockIdx.y * 128, bn = blockIdx.x * 128;
    float acc[2][8][4] = {};

    // ldmatrix per-thread address offsets (bytes, relative to buf base)
    int lq = lane >> 3, lr = lane & 7;
    uint32_t smem_base = smem_u32(smem);
    // A x4: {rows +0, col kk} {rows +8, col kk} {rows +0, kk+4} {rows +8, kk+4}
    uint32_t aOff = ((wm * 32 + (lq & 1) * 8 + lr) * SROW_W + (lq >> 1) * 4) * 4;
    // B x4: {ni rows, kk} {ni rows, kk+4} {ni+1 rows, kk} {ni+1 rows, kk+4}
    uint32_t bOff = ((wn * 64 + (lq >> 1) * 8 + lr) * SROW_W + (lq & 1) * 4) * 4;

    auto stage = [&](int buf, int k0) {
        float* bA = sA + buf * SA_SZ;
        float* bB = sB + buf * SB_SZ;
        int ksh = 0, acol0 = k0;
        if constexpr (CONV) { ksh = (k0 >> 8) - 2; acol0 = k0 & 255; }
#pragma unroll
        for (int h = 0; h < 2; h++) {
            int q = tid + h * 256;
            int r = q >> 2, quad = q & 3;
            uint32_t dst = smem_u32(bA + r * SROW_W + quad * 4);
            const float* src;
            int sz = 16;
            if constexpr (CONV) {
                int rm = bm + r, srow = rm + ksh;
                if (srow < 0 || (srow / L) != (rm / L)) { srow = rm; sz = 0; }
                src = A + (size_t)srow * astride + acol0 + quad * 4;
            } else {
                src = A + (size_t)(bm + r) * astride + k0 + quad * 4;
            }
            asm volatile("cp.async.ca.shared.global [%0], [%1], 16, %2;"
                         :: "r"(dst), "l"(src), "r"(sz) : "memory");
        }
#pragma unroll
        for (int h = 0; h < 2; h++) {
            int q = tid + h * 256;
            int r = q >> 2, quad = q & 3;        // r = n row, quad = k chunk
            uint32_t dst = smem_u32(bB + r * SROW_W + quad * 4);
            const float* src = BwT + (size_t)(bn + r) * K + k0 + quad * 4;
            asm volatile("cp.async.ca.shared.global [%0], [%1], 16;"
                         :: "r"(dst), "l"(src) : "memory");
        }
        asm volatile("cp.async.commit_group;" ::: "memory");
    };

    int KT = K >> 4;
    stage(0, 0);
    stage(1, 16);
    for (int kt = 0; kt < KT; kt++) {
        if (kt + 1 < KT)
            asm volatile("cp.async.wait_group 1;" ::: "memory");
        else
            asm volatile("cp.async.wait_group 0;" ::: "memory");
        __syncthreads();
        int buf = kt % 3;
        uint32_t aAddr = smem_base + (buf * SA_SZ) * 4 + aOff;
        uint32_t bAddr = smem_base + (3 * SA_SZ + buf * SB_SZ) * 4 + bOff;
#pragma unroll
        for (int kk = 0; kk < 16; kk += 8) {
            unsigned a[2][4], b[8][2];
            ldsm4(a[0], aAddr + kk * 4);
            ldsm4(a[1], aAddr + 16 * SROW_W * 4 + kk * 4);
#pragma unroll
            for (int p = 0; p < 4; p++) {
                unsigned t4[4];
                ldsm4(t4, bAddr + p * 16 * SROW_W * 4 + kk * 4);
                b[2 * p][0] = t4[0]; b[2 * p][1] = t4[1];
                b[2 * p + 1][0] = t4[2]; b[2 * p + 1][1] = t4[3];
            }
#pragma unroll
            for (int mi = 0; mi < 2; mi++)
#pragma unroll
                for (int ni = 0; ni < 8; ni++)
                    mma_tf32(acc[mi][ni], a[mi], b[ni]);
        }
        if (kt + 2 < KT) stage((kt + 2) % 3, (kt + 2) << 4);
    }

    if constexpr (!CONV) {
#pragma unroll
        for (int mi = 0; mi < 2; mi++) {
            int r0 = bm + wm * 32 + mi * 16 + gid;
#pragma unroll
            for (int ni = 0; ni < 8; ni++) {
                int c0 = bn + wn * 64 + ni * 8 + tg * 2;
                *(float2*)(C + (size_t)r0 * N + c0) = make_float2(acc[mi][ni][0], acc[mi][ni][1]);
                *(float2*)(C + (size_t)(r0 + 8) * N + c0) = make_float2(acc[mi][ni][2], acc[mi][ni][3]);
            }
        }
    } else {
        bool wr = (gid & 1) == 0;
#pragma unroll
        for (int mi = 0; mi < 2; mi++) {
            int rbase = bm + wm * 32 + mi * 16 + gid;
#pragma unroll
            for (int ni = 0; ni < 8; ni++) {
                int c0 = bn + wn * 64 + ni * 8 + tg * 2;
                float b0 = bias[c0], b1 = bias[c0 + 1];
                float u0 = fmaxf(acc[mi][ni][0] + b0, 0.f);
                float u1 = fmaxf(acc[mi][ni][1] + b1, 0.f);
                float u2 = fmaxf(acc[mi][ni][2] + b0, 0.f);
                float u3 = fmaxf(acc[mi][ni][3] + b1, 0.f);
                float p0 = fmaxf(u0, __shfl_xor_sync(0xffffffffu, u0, 4));
                float p1 = fmaxf(u1, __shfl_xor_sync(0xffffffffu, u1, 4));
                float p2 = fmaxf(u2, __shfl_xor_sync(0xffffffffu, u2, 4));
                float p3 = fmaxf(u3, __shfl_xor_sync(0xffffffffu, u3, 4));
                if constexpr (!FIN) {
                    p0 = rndtf32(p0); p1 = rndtf32(p1);
                    p2 = rndtf32(p2); p3 = rndtf32(p3);
                }
                if (wr) {
                    *(float2*)(C + (size_t)(rbase >> 1) * 256 + c0) = make_float2(p0, p1);
                    *(float2*)(C + (size_t)((rbase + 8) >> 1) * 256 + c0) = make_float2(p2, p3);
                }
            }
        }
    }
}

// ---------------------------------------------------------------------------
extern "C" void kernel_launch(void* const* d_in, const int* in_sizes, int n_in,
                              void* d_out, int out_size) {
    const float* data = (const float*)d_in[0];
    const int*   ei0  = (const int*)d_in[2];
    const int*   ei1  = (const int*)d_in[3];
    const float* W0   = (const float*)d_in[4];
    const float* b0   = (const float*)d_in[5];
    const float* Wc0  = (const float*)d_in[6];
    const float* bc0  = (const float*)d_in[7];
    const float* W1   = (const float*)d_in[8];
    const float* b1   = (const float*)d_in[9];
    const float* Wc1  = (const float*)d_in[10];
    const float* bc1  = (const float*)d_in[11];
    float* out = (float*)d_out;

    void* sp = nullptr;
    cudaGetSymbolAddress(&sp, g_scratch);
    float* S     = (float*)sp;
    float* x0    = S + OFF_X0;
    float* AB0   = S + OFF_AB0;
    float* out0  = S + OFF_OUT0;
    float* x1    = S + OFF_X1;
    float* AB1   = S + OFF_AB1;
    float* out1  = S + OFF_OUT1;
    float* WcT0  = S + OFF_WCAT0;
    float* WcT1  = S + OFF_WCAT1;
    float* WtT0  = S + OFF_WT0;
    float* WtT1  = S + OFF_WT1;
    int* bkt0 = (int*)(S + OFF_BKT0);
    int* bkt1 = (int*)(S + OFF_BKT1);
    int* cnt0 = (int*)(S + OFF_CNT0);
    int* cnt1 = (int*)(S + OFF_CNT1);

    static bool attr_done = false;
    if (!attr_done) {
        cudaFuncSetAttribute(mma_gemm<0, 1, 0>, cudaFuncAttributeMaxDynamicSharedMemorySize, GEMM_SMEM);
        cudaFuncSetAttribute(mma_gemm<1, 128, 0>, cudaFuncAttributeMaxDynamicSharedMemorySize, GEMM_SMEM);
        cudaFuncSetAttribute(mma_gemm<1, 64, 1>, cudaFuncAttributeMaxDynamicSharedMemorySize, GEMM_SMEM);
        attr_done = true;
    }

    prep_weights<<<3328, 256>>>(W0, W1, Wc0, Wc1, WcT0, WcT1, WtT0, WtT1);
    permute_in<<<(M0 * 128) / 256, 256>>>(data, x0);
    zero_cnt<<<(M0 + M1) / 256, 256>>>(cnt0);   // cnt0,cnt1 contiguous

    fill_edges<<<E0 / 256, 256>>>(ei0, E0, cnt0, bkt0);
    fill_edges<<<E1 / 256, 256>>>(ei1, E1, cnt1, bkt1);

    // layer 0
    mma_gemm<0, 1, 0><<<dim3(4, M0 / 128), 256, GEMM_SMEM>>>(x0, WcT0, nullptr, AB0, 512, 128, 128);
    gather_max<<<M0 / 8, 256>>>(cnt0, bkt0, AB0, b0, out0, M0);
    mma_gemm<1, 128, 0><<<dim3(2, M0 / 128), 256, GEMM_SMEM>>>(out0, WtT0, bc0, x1, 256, 1280, 256);

    // layer 1
    mma_gemm<0, 1, 0><<<dim3(4, M1 / 128), 256, GEMM_SMEM>>>(x1, WcT1, nullptr, AB1, 512, 256, 256);
    gather_max<<<M1 / 8, 256>>>(cnt1, bkt1, AB1, b1, out1, M1);
    mma_gemm<1, 64, 1><<<dim3(2, M1 / 128), 256, GEMM_SMEM>>>(out1, WtT1, bc1, out, 256, 1280, 256);
}